// round 1
// baseline (speedup 1.0000x reference)
#include <cuda_runtime.h>
#include <math.h>

#define T_SEQ   2048
#define C_EMB   4096
#define QKV_N   6144
#define FFN_N   11008
#define N_HEAD_ 32
#define HEAD_D  128

// ---------------- scratch (static device globals; allocation-free) ----------------
__device__ float g_n1[T_SEQ * C_EMB];
__device__ float g_qkv[T_SEQ * QKV_N];
__device__ float g_scaling[T_SEQ * C_EMB];
__device__ float g_scale_t[N_HEAD_ * T_SEQ];
__device__ float g_y[T_SEQ * C_EMB];
__device__ float g_resid[T_SEQ * C_EMB];
__device__ float g_n2[T_SEQ * C_EMB];
__device__ float g_gate[T_SEQ * FFN_N];
__device__ float g_h[T_SEQ * FFN_N];

// ---------------- RMSNorm: one block per row of 4096 ----------------
__global__ __launch_bounds__(256) void rmsnorm_kernel(const float* __restrict__ x,
                                                      const float* __restrict__ w,
                                                      float* __restrict__ out) {
    const long row = blockIdx.x;
    const float* xr = x + row * C_EMB;
    float* orow = out + row * C_EMB;
    const int tid = threadIdx.x;

    float4 v[4];
    float ss = 0.f;
#pragma unroll
    for (int i = 0; i < 4; i++) {
        v[i] = *(const float4*)(xr + tid * 4 + i * 1024);
        ss += v[i].x * v[i].x + v[i].y * v[i].y + v[i].z * v[i].z + v[i].w * v[i].w;
    }
#pragma unroll
    for (int o = 16; o; o >>= 1) ss += __shfl_xor_sync(0xffffffffu, ss, o);
    __shared__ float red[8];
    if ((tid & 31) == 0) red[tid >> 5] = ss;
    __syncthreads();
    float tot = red[0] + red[1] + red[2] + red[3] + red[4] + red[5] + red[6] + red[7];
    const float inv = rsqrtf(tot * (1.f / 4096.f) + 1e-5f);
#pragma unroll
    for (int i = 0; i < 4; i++) {
        float4 wv = *(const float4*)(w + tid * 4 + i * 1024);
        float4 o;
        o.x = v[i].x * inv * wv.x;
        o.y = v[i].y * inv * wv.y;
        o.z = v[i].z * inv * wv.z;
        o.w = v[i].w * inv * wv.w;
        *(float4*)(orow + tid * 4 + i * 1024) = o;
    }
}

// ---------------- SGEMM NT: C[M,N] = A[M,K] * W[N,K]^T (+epilogue) ----------------
// EPI: 0 none, 1 relu(acc+bias[n]), 2 acc+extra[m,n], 3 silu(extra[m,n])*acc
template <int EPI>
__global__ __launch_bounds__(256, 2)
void sgemm_nt(const float* __restrict__ A, const float* __restrict__ W,
              float* __restrict__ C, int M, int N, int K,
              const float* __restrict__ extra, const float* __restrict__ bias) {
    __shared__ float As[16][132];
    __shared__ float Bs[16][132];
    const int tid = threadIdx.x;
    const int bm = blockIdx.y * 128;
    const int bn = blockIdx.x * 128;
    const int tx = tid & 15;
    const int ty = tid >> 4;
    const int lrow = tid >> 2;
    const int lk = (tid & 3) << 2;

    const float* Ap = A + (long)(bm + lrow) * K + lk;
    const float* Bp = W + (long)(bn + lrow) * K + lk;

    float acc[8][8];
#pragma unroll
    for (int i = 0; i < 8; i++)
#pragma unroll
        for (int j = 0; j < 8; j++) acc[i][j] = 0.f;

    float4 a0 = *(const float4*)(Ap);
    float4 a1 = *(const float4*)(Ap + 64l * K);
    float4 b0 = *(const float4*)(Bp);
    float4 b1 = *(const float4*)(Bp + 64l * K);

    for (int k0 = 0; k0 < K; k0 += 16) {
        As[lk + 0][lrow] = a0.x; As[lk + 1][lrow] = a0.y; As[lk + 2][lrow] = a0.z; As[lk + 3][lrow] = a0.w;
        As[lk + 0][lrow + 64] = a1.x; As[lk + 1][lrow + 64] = a1.y; As[lk + 2][lrow + 64] = a1.z; As[lk + 3][lrow + 64] = a1.w;
        Bs[lk + 0][lrow] = b0.x; Bs[lk + 1][lrow] = b0.y; Bs[lk + 2][lrow] = b0.z; Bs[lk + 3][lrow] = b0.w;
        Bs[lk + 0][lrow + 64] = b1.x; Bs[lk + 1][lrow + 64] = b1.y; Bs[lk + 2][lrow + 64] = b1.z; Bs[lk + 3][lrow + 64] = b1.w;
        __syncthreads();
        if (k0 + 16 < K) {
            a0 = *(const float4*)(Ap + k0 + 16);
            a1 = *(const float4*)(Ap + 64l * K + k0 + 16);
            b0 = *(const float4*)(Bp + k0 + 16);
            b1 = *(const float4*)(Bp + 64l * K + k0 + 16);
        }
#pragma unroll
        for (int kk = 0; kk < 16; kk++) {
            float af[8], bf[8];
            *(float4*)(af)     = *(const float4*)&As[kk][ty * 4];
            *(float4*)(af + 4) = *(const float4*)&As[kk][64 + ty * 4];
            *(float4*)(bf)     = *(const float4*)&Bs[kk][tx * 4];
            *(float4*)(bf + 4) = *(const float4*)&Bs[kk][64 + tx * 4];
#pragma unroll
            for (int i = 0; i < 8; i++)
#pragma unroll
                for (int j = 0; j < 8; j++) acc[i][j] += af[i] * bf[j];
        }
        __syncthreads();
    }

#pragma unroll
    for (int i = 0; i < 8; i++) {
        const int row = bm + ((i < 4) ? (ty * 4 + i) : (64 + ty * 4 + (i - 4)));
#pragma unroll
        for (int jj = 0; jj < 2; jj++) {
            const int col = bn + (jj ? (64 + tx * 4) : (tx * 4));
            float4 v;
            float* pv = &v.x;
#pragma unroll
            for (int u = 0; u < 4; u++) {
                float a = acc[i][jj * 4 + u];
                const int c = col + u;
                if (EPI == 1) { a += bias[c]; a = fmaxf(a, 0.f); }
                else if (EPI == 2) { a += extra[(long)row * N + c]; }
                else if (EPI == 3) { float g = extra[(long)row * N + c]; a *= g / (1.f + __expf(-g)); }
                pv[u] = a;
            }
            *(float4*)(C + (long)row * N + col) = v;
        }
    }
}

// ---------------- RoPE in-place on q(4 slots)+k(1 slot) of qkv ----------------
__global__ __launch_bounds__(256) void rope_kernel(float* __restrict__ qkv,
                                                   const float* __restrict__ cosb,
                                                   const float* __restrict__ sinb) {
    const int idx = blockIdx.x * 256 + threadIdx.x;  // 2048*8*5*64 total
    const int d = idx & 63;
    int vec = idx >> 6;
    const int s = vec % 5; vec /= 5;
    const int g = vec & 7;
    const int t = vec >> 3;
    const long base = (long)t * QKV_N + g * 768 + s * 128;
    const float x1 = qkv[base + d];
    const float x2 = qkv[base + d + 64];
    const float c1 = cosb[t * 128 + d], s1 = sinb[t * 128 + d];
    const float c2 = cosb[t * 128 + d + 64], s2 = sinb[t * 128 + d + 64];
    qkv[base + d]      = x1 * c1 - x2 * s1;
    qkv[base + d + 64] = x2 * c2 + x1 * s2;
}

// ---------------- scale_t[h][t] = mean_d relu_scaling[t][h*128+d] ----------------
__global__ __launch_bounds__(256) void scale_mean_kernel(const float* __restrict__ scaling,
                                                         float* __restrict__ scale_t) {
    const int wid = (blockIdx.x * 256 + threadIdx.x) >> 5;
    const int lane = threadIdx.x & 31;
    const int t = wid >> 5;
    const int h = wid & 31;
    const float4 v = *(const float4*)(scaling + (long)t * C_EMB + h * 128 + lane * 4);
    float s = v.x + v.y + v.z + v.w;
#pragma unroll
    for (int o = 16; o; o >>= 1) s += __shfl_xor_sync(0xffffffffu, s, o);
    if (lane == 0) scale_t[h * T_SEQ + t] = s * (1.f / 128.f);
}

// ---------------- flash attention (non-causal), BQ=64, BK=64 ----------------
// smem: Sq[64*128] + Sk[64*128 swz] + Sv[64*128 swz] + S[64*65] + m/l/c[64 each]
#define FLASH_SMEM_FLOATS (3 * 64 * 128 + 64 * 65 + 3 * 64)
#define FLASH_SMEM_BYTES (FLASH_SMEM_FLOATS * 4)

__device__ __forceinline__ int swz(int row, int dv) {
    return row * 128 + ((dv ^ ((row >> 2) & 7)) << 2);
}

__global__ __launch_bounds__(256, 1)
void flash_kernel(const float* __restrict__ qkv, const float* __restrict__ scale_t,
                  float* __restrict__ y) {
    extern __shared__ float sm[];
    float* Sq = sm;                    // plain [64][128]
    float* Sk = Sq + 64 * 128;         // swizzled
    float* Sv = Sk + 64 * 128;         // swizzled
    float* S  = Sv + 64 * 128;         // [64][65]
    float* m_s = S + 64 * 65;
    float* l_s = m_s + 64;
    float* c_s = l_s + 64;

    const int tid = threadIdx.x;
    const int qb = blockIdx.x;
    const int h = blockIdx.y;
    const int g = h >> 2, s = h & 3;
    const float sf = 0.08838834764831845f;  // 1/sqrt(128)

    // load Q tile, pre-scaled by sf * scale_t[h][t]
#pragma unroll
    for (int it = 0; it < 8; ++it) {
        const int f = tid + it * 256;
        const int qi = f >> 5;
        const int dv = f & 31;
        const int t = qb * 64 + qi;
        const float sc = sf * scale_t[h * T_SEQ + t];
        float4 v = *(const float4*)(qkv + (long)t * QKV_N + g * 768 + s * 128 + dv * 4);
        v.x *= sc; v.y *= sc; v.z *= sc; v.w *= sc;
        *(float4*)(Sq + qi * 128 + dv * 4) = v;
    }
    if (tid < 64) { m_s[tid] = -1e30f; l_s[tid] = 0.f; }

    float acc[4][8];
#pragma unroll
    for (int i = 0; i < 4; i++)
#pragma unroll
        for (int j = 0; j < 8; j++) acc[i][j] = 0.f;

    const int r0 = (tid & 15) * 4;   // PV rows
    const int c0 = (tid >> 4) * 8;   // PV cols
    const int q0 = (tid >> 4) * 4;   // S rows
    const int k0 = (tid & 15) * 4;   // S cols
    __syncthreads();

    for (int kt = 0; kt < 32; ++kt) {
        // load K/V tile (coalesced, swizzled store)
#pragma unroll
        for (int it = 0; it < 8; ++it) {
            const int f = tid + it * 256;
            const int kj = f >> 5;
            const int dv = f & 31;
            const long base = (long)(kt * 64 + kj) * QKV_N + g * 768;
            *(float4*)(Sk + swz(kj, dv)) = *(const float4*)(qkv + base + 4 * 128 + dv * 4);
            *(float4*)(Sv + swz(kj, dv)) = *(const float4*)(qkv + base + 5 * 128 + dv * 4);
        }
        __syncthreads();

        // S = Sq @ Sk^T : 4x4 per thread
        float sacc[4][4];
#pragma unroll
        for (int i = 0; i < 4; i++)
#pragma unroll
            for (int j = 0; j < 4; j++) sacc[i][j] = 0.f;
        for (int d = 0; d < 128; d += 4) {
            float4 a[4], b[4];
#pragma unroll
            for (int i = 0; i < 4; i++) a[i] = *(const float4*)(Sq + (q0 + i) * 128 + d);
#pragma unroll
            for (int j = 0; j < 4; j++) b[j] = *(const float4*)(Sk + swz(k0 + j, d >> 2));
#pragma unroll
            for (int i = 0; i < 4; i++)
#pragma unroll
                for (int j = 0; j < 4; j++)
                    sacc[i][j] += a[i].x * b[j].x + a[i].y * b[j].y + a[i].z * b[j].z + a[i].w * b[j].w;
        }
#pragma unroll
        for (int i = 0; i < 4; i++)
#pragma unroll
            for (int j = 0; j < 4; j++) S[(q0 + i) * 65 + k0 + j] = sacc[i][j];
        __syncthreads();

        // online softmax (4 threads per row)
        {
            const int r = tid >> 2, qd = tid & 3;
            float* row = S + r * 65;
            float tmax = -1e30f;
            for (int j = qd * 16; j < qd * 16 + 16; j++) tmax = fmaxf(tmax, row[j]);
            tmax = fmaxf(tmax, __shfl_xor_sync(0xffffffffu, tmax, 1));
            tmax = fmaxf(tmax, __shfl_xor_sync(0xffffffffu, tmax, 2));
            const float m_old = m_s[r];
            const float m_new = fmaxf(m_old, tmax);
            float psum = 0.f;
            for (int j = qd * 16; j < qd * 16 + 16; j++) {
                const float p = __expf(row[j] - m_new);
                row[j] = p;
                psum += p;
            }
            psum += __shfl_xor_sync(0xffffffffu, psum, 1);
            psum += __shfl_xor_sync(0xffffffffu, psum, 2);
            if (qd == 0) {
                const float corr = __expf(m_old - m_new);
                l_s[r] = l_s[r] * corr + psum;
                m_s[r] = m_new;
                c_s[r] = corr;
            }
        }
        __syncthreads();

        // acc = acc*corr + P @ V
        float cr[4];
#pragma unroll
        for (int i = 0; i < 4; i++) cr[i] = c_s[r0 + i];
#pragma unroll
        for (int i = 0; i < 4; i++)
#pragma unroll
            for (int j = 0; j < 8; j++) acc[i][j] *= cr[i];
        for (int kj = 0; kj < 64; ++kj) {
            float p[4];
#pragma unroll
            for (int i = 0; i < 4; i++) p[i] = S[(r0 + i) * 65 + kj];
            const float4 v0 = *(const float4*)(Sv + swz(kj, c0 >> 2));
            const float4 v1 = *(const float4*)(Sv + swz(kj, (c0 >> 2) + 1));
#pragma unroll
            for (int i = 0; i < 4; i++) {
                acc[i][0] += p[i] * v0.x; acc[i][1] += p[i] * v0.y;
                acc[i][2] += p[i] * v0.z; acc[i][3] += p[i] * v0.w;
                acc[i][4] += p[i] * v1.x; acc[i][5] += p[i] * v1.y;
                acc[i][6] += p[i] * v1.z; acc[i][7] += p[i] * v1.w;
            }
        }
        __syncthreads();
    }

    // write y[t][h*128 + c]
#pragma unroll
    for (int i = 0; i < 4; i++) {
        const int t = qb * 64 + r0 + i;
        const float inv_l = 1.f / l_s[r0 + i];
        float4 o0, o1;
        o0.x = acc[i][0] * inv_l; o0.y = acc[i][1] * inv_l;
        o0.z = acc[i][2] * inv_l; o0.w = acc[i][3] * inv_l;
        o1.x = acc[i][4] * inv_l; o1.y = acc[i][5] * inv_l;
        o1.z = acc[i][6] * inv_l; o1.w = acc[i][7] * inv_l;
        *(float4*)(y + (long)t * C_EMB + h * 128 + c0)     = o0;
        *(float4*)(y + (long)t * C_EMB + h * 128 + c0 + 4) = o1;
    }
}

// ---------------- host launcher ----------------
extern "C" void kernel_launch(void* const* d_in, const int* in_sizes, int n_in,
                              void* d_out, int out_size) {
    const float* x       = (const float*)d_in[0];
    const float* cosb    = (const float*)d_in[1];
    const float* sinb    = (const float*)d_in[2];
    const float* norm1_w = (const float*)d_in[3];
    const float* norm2_w = (const float*)d_in[4];
    const float* attn_w  = (const float*)d_in[5];
    const float* proj_w  = (const float*)d_in[6];
    const float* scale_w = (const float*)d_in[7];
    const float* scale_b = (const float*)d_in[8];
    const float* gate_w  = (const float*)d_in[9];
    const float* up_w    = (const float*)d_in[10];
    const float* down_w  = (const float*)d_in[11];
    float* out = (float*)d_out;

    float *n1, *qkv, *scaling, *scale_t, *y, *resid, *n2, *gate, *hbuf;
    cudaGetSymbolAddress((void**)&n1, g_n1);
    cudaGetSymbolAddress((void**)&qkv, g_qkv);
    cudaGetSymbolAddress((void**)&scaling, g_scaling);
    cudaGetSymbolAddress((void**)&scale_t, g_scale_t);
    cudaGetSymbolAddress((void**)&y, g_y);
    cudaGetSymbolAddress((void**)&resid, g_resid);
    cudaGetSymbolAddress((void**)&n2, g_n2);
    cudaGetSymbolAddress((void**)&gate, g_gate);
    cudaGetSymbolAddress((void**)&hbuf, g_h);

    cudaFuncSetAttribute(flash_kernel, cudaFuncAttributeMaxDynamicSharedMemorySize,
                         FLASH_SMEM_BYTES);

    // n1 = rmsnorm(x, norm1_w)
    rmsnorm_kernel<<<T_SEQ, 256>>>(x, norm1_w, n1);
    // qkv = n1 @ attn_w^T
    sgemm_nt<0><<<dim3(QKV_N / 128, T_SEQ / 128), 256>>>(n1, attn_w, qkv, T_SEQ, QKV_N, C_EMB, nullptr, nullptr);
    // scaling = relu(n1 @ scale_w^T + scale_b)
    sgemm_nt<1><<<dim3(C_EMB / 128, T_SEQ / 128), 256>>>(n1, scale_w, scaling, T_SEQ, C_EMB, C_EMB, nullptr, scale_b);
    // rope in-place on q and k slots
    rope_kernel<<<(T_SEQ * 8 * 5 * 64) / 256, 256>>>(qkv, cosb, sinb);
    // scale_t[h][t] = mean over head dims
    scale_mean_kernel<<<(T_SEQ * N_HEAD_) / 8, 256>>>(scaling, scale_t);
    // flash attention -> y [T][C] (head-major within row)
    flash_kernel<<<dim3(T_SEQ / 64, N_HEAD_), 256, FLASH_SMEM_BYTES>>>(qkv, scale_t, y);
    // resid = x + y @ proj_w^T
    sgemm_nt<2><<<dim3(C_EMB / 128, T_SEQ / 128), 256>>>(y, proj_w, resid, T_SEQ, C_EMB, C_EMB, x, nullptr);
    // n2 = rmsnorm(resid, norm2_w)
    rmsnorm_kernel<<<T_SEQ, 256>>>(resid, norm2_w, n2);
    // gate = n2 @ gate_w^T
    sgemm_nt<0><<<dim3(FFN_N / 128, T_SEQ / 128), 256>>>(n2, gate_w, gate, T_SEQ, FFN_N, C_EMB, nullptr, nullptr);
    // hbuf = silu(gate) * (n2 @ up_w^T)
    sgemm_nt<3><<<dim3(FFN_N / 128, T_SEQ / 128), 256>>>(n2, up_w, hbuf, T_SEQ, FFN_N, C_EMB, gate, nullptr);
    // out = resid + hbuf @ down_w^T
    sgemm_nt<2><<<dim3(C_EMB / 128, T_SEQ / 128), 256>>>(hbuf, down_w, out, T_SEQ, C_EMB, FFN_N, resid, nullptr);
}

// round 2
// speedup vs baseline: 2.0017x; 2.0017x over previous
#include <cuda_runtime.h>
#include <math.h>

#define T_SEQ   2048
#define C_EMB   4096
#define QKV_N   6144
#define FFN_N   11008
#define N_HEAD_ 32
#define HEAD_D  128

// ---------------- scratch (static device globals; allocation-free) ----------------
__device__ float g_n1[T_SEQ * C_EMB];
__device__ float g_qkv[T_SEQ * QKV_N];
__device__ float g_scaling[T_SEQ * C_EMB];
__device__ float g_scale_t[N_HEAD_ * T_SEQ];
__device__ float g_y[T_SEQ * C_EMB];
__device__ float g_resid[T_SEQ * C_EMB];
__device__ float g_n2[T_SEQ * C_EMB];
__device__ float g_gate[T_SEQ * FFN_N];
__device__ float g_h[T_SEQ * FFN_N];

// ---------------- RMSNorm ----------------
__global__ __launch_bounds__(256) void rmsnorm_kernel(const float* __restrict__ x,
                                                      const float* __restrict__ w,
                                                      float* __restrict__ out) {
    const long row = blockIdx.x;
    const float* xr = x + row * C_EMB;
    float* orow = out + row * C_EMB;
    const int tid = threadIdx.x;

    float4 v[4];
    float ss = 0.f;
#pragma unroll
    for (int i = 0; i < 4; i++) {
        v[i] = *(const float4*)(xr + tid * 4 + i * 1024);
        ss += v[i].x * v[i].x + v[i].y * v[i].y + v[i].z * v[i].z + v[i].w * v[i].w;
    }
#pragma unroll
    for (int o = 16; o; o >>= 1) ss += __shfl_xor_sync(0xffffffffu, ss, o);
    __shared__ float red[8];
    if ((tid & 31) == 0) red[tid >> 5] = ss;
    __syncthreads();
    float tot = red[0] + red[1] + red[2] + red[3] + red[4] + red[5] + red[6] + red[7];
    const float inv = rsqrtf(tot * (1.f / 4096.f) + 1e-5f);
#pragma unroll
    for (int i = 0; i < 4; i++) {
        float4 wv = *(const float4*)(w + tid * 4 + i * 1024);
        float4 o;
        o.x = v[i].x * inv * wv.x;
        o.y = v[i].y * inv * wv.y;
        o.z = v[i].z * inv * wv.z;
        o.w = v[i].w * inv * wv.w;
        *(float4*)(orow + tid * 4 + i * 1024) = o;
    }
}

// ---------------- tf32 tensor-core GEMM helpers ----------------
__device__ __forceinline__ unsigned cvt_tf32(float f) {
    unsigned u;
    asm("cvt.rna.tf32.f32 %0, %1;" : "=r"(u) : "f"(f));
    return u;
}

__device__ __forceinline__ void mma_tf32(float* c, const unsigned* a, const unsigned* b) {
    asm volatile(
        "mma.sync.aligned.m16n8k8.row.col.f32.tf32.tf32.f32 "
        "{%0,%1,%2,%3},{%4,%5,%6,%7},{%8,%9},{%0,%1,%2,%3};"
        : "+f"(c[0]), "+f"(c[1]), "+f"(c[2]), "+f"(c[3])
        : "r"(a[0]), "r"(a[1]), "r"(a[2]), "r"(a[3]), "r"(b[0]), "r"(b[1]));
}

__device__ __forceinline__ void cp_async16(void* smem_ptr, const void* gptr) {
    unsigned s = (unsigned)__cvta_generic_to_shared(smem_ptr);
    asm volatile("cp.async.cg.shared.global [%0], [%1], 16;" :: "r"(s), "l"(gptr));
}
#define CP_COMMIT() asm volatile("cp.async.commit_group;")
#define CP_WAIT0()  asm volatile("cp.async.wait_group 0;")

#define LDSS 20  // smem row stride (16 + 4 pad): bank = (20*gi+ci)%32 covers all 32

// ---------------- tf32 GEMM NT: C[M,N] = A[M,K] * W[N,K]^T (+epilogue) ----------------
// EPI: 0 none, 1 relu(acc+bias[n]), 2 acc+extra[m,n], 3 silu(extra[m,n])*acc
template <int EPI>
__global__ __launch_bounds__(256, 2)
void tf32_gemm(const float* __restrict__ A, const float* __restrict__ W,
               float* __restrict__ C, int M, int N, int K,
               const float* __restrict__ extra, const float* __restrict__ bias) {
    __shared__ float As[2][128 * LDSS];
    __shared__ float Bs[2][128 * LDSS];

    const int tid  = threadIdx.x;
    const int bm   = blockIdx.y * 128;
    const int bn   = blockIdx.x * 128;
    const int warp = tid >> 5;
    const int lane = tid & 31;
    const int wm   = (warp & 1) * 64;   // 2 warps along M
    const int wn   = (warp >> 1) * 32;  // 4 warps along N
    const int gi   = lane >> 2;         // 0..7
    const int ci   = lane & 3;          // 0..3

    // cp.async staging coords
    const int lrow = tid >> 2;          // 0..63
    const int lcol = (tid & 3) * 4;     // 0,4,8,12
    const float* Ap = A + (long)(bm + lrow) * K + lcol;
    const float* Bp = W + (long)(bn + lrow) * K + lcol;
    const int sw0 = lrow * LDSS + lcol;
    const int sw1 = (lrow + 64) * LDSS + lcol;

    float acc[4][4][4];
#pragma unroll
    for (int mt = 0; mt < 4; mt++)
#pragma unroll
        for (int nt = 0; nt < 4; nt++)
#pragma unroll
            for (int u = 0; u < 4; u++) acc[mt][nt][u] = 0.f;

    // prologue: stage buffer 0
    cp_async16(&As[0][sw0], Ap);
    cp_async16(&As[0][sw1], Ap + 64l * K);
    cp_async16(&Bs[0][sw0], Bp);
    cp_async16(&Bs[0][sw1], Bp + 64l * K);
    CP_COMMIT();

    const int steps = K >> 4;
    int buf = 0;
    for (int it = 0; it < steps; ++it) {
        CP_WAIT0();
        __syncthreads();
        if (it + 1 < steps) {
            const long ko = (long)(it + 1) << 4;
            cp_async16(&As[buf ^ 1][sw0], Ap + ko);
            cp_async16(&As[buf ^ 1][sw1], Ap + 64l * K + ko);
            cp_async16(&Bs[buf ^ 1][sw0], Bp + ko);
            cp_async16(&Bs[buf ^ 1][sw1], Bp + 64l * K + ko);
            CP_COMMIT();
        }
        const float* as = As[buf];
        const float* bs = Bs[buf];
#pragma unroll
        for (int kc = 0; kc < 2; ++kc) {
            const int kb = kc * 8;
            unsigned af[4][4], bf[4][2];
#pragma unroll
            for (int mt = 0; mt < 4; ++mt) {
                const int r = wm + mt * 16 + gi;
                af[mt][0] = cvt_tf32(as[r * LDSS + kb + ci]);
                af[mt][1] = cvt_tf32(as[(r + 8) * LDSS + kb + ci]);
                af[mt][2] = cvt_tf32(as[r * LDSS + kb + ci + 4]);
                af[mt][3] = cvt_tf32(as[(r + 8) * LDSS + kb + ci + 4]);
            }
#pragma unroll
            for (int nt = 0; nt < 4; ++nt) {
                const int n = wn + nt * 8 + gi;
                bf[nt][0] = cvt_tf32(bs[n * LDSS + kb + ci]);
                bf[nt][1] = cvt_tf32(bs[n * LDSS + kb + ci + 4]);
            }
#pragma unroll
            for (int mt = 0; mt < 4; ++mt)
#pragma unroll
                for (int nt = 0; nt < 4; ++nt)
                    mma_tf32(acc[mt][nt], af[mt], bf[nt]);
        }
        buf ^= 1;
        __syncthreads();
    }

    // epilogue: c0,c1 at (row, 2ci), c2,c3 at (row+8, 2ci)
#pragma unroll
    for (int mt = 0; mt < 4; ++mt) {
        const int row  = bm + wm + mt * 16 + gi;
        const int row2 = row + 8;
#pragma unroll
        for (int nt = 0; nt < 4; ++nt) {
            const int col = bn + wn + nt * 8 + ci * 2;
            float v[4] = {acc[mt][nt][0], acc[mt][nt][1], acc[mt][nt][2], acc[mt][nt][3]};
            if (EPI == 1) {
                const float b0 = bias[col], b1 = bias[col + 1];
                v[0] = fmaxf(v[0] + b0, 0.f); v[1] = fmaxf(v[1] + b1, 0.f);
                v[2] = fmaxf(v[2] + b0, 0.f); v[3] = fmaxf(v[3] + b1, 0.f);
            } else if (EPI == 2) {
                const float2 e0 = *(const float2*)(extra + (long)row * N + col);
                const float2 e1 = *(const float2*)(extra + (long)row2 * N + col);
                v[0] += e0.x; v[1] += e0.y; v[2] += e1.x; v[3] += e1.y;
            } else if (EPI == 3) {
                const float2 g0 = *(const float2*)(extra + (long)row * N + col);
                const float2 g1 = *(const float2*)(extra + (long)row2 * N + col);
                v[0] *= g0.x / (1.f + __expf(-g0.x));
                v[1] *= g0.y / (1.f + __expf(-g0.y));
                v[2] *= g1.x / (1.f + __expf(-g1.x));
                v[3] *= g1.y / (1.f + __expf(-g1.y));
            }
            float2 o0 = {v[0], v[1]}, o1 = {v[2], v[3]};
            *(float2*)(C + (long)row * N + col)  = o0;
            *(float2*)(C + (long)row2 * N + col) = o1;
        }
    }
}

// ---------------- RoPE in-place on q(4 slots)+k(1 slot) of qkv ----------------
__global__ __launch_bounds__(256) void rope_kernel(float* __restrict__ qkv,
                                                   const float* __restrict__ cosb,
                                                   const float* __restrict__ sinb) {
    const int idx = blockIdx.x * 256 + threadIdx.x;
    const int d = idx & 63;
    int vec = idx >> 6;
    const int s = vec % 5; vec /= 5;
    const int g = vec & 7;
    const int t = vec >> 3;
    const long base = (long)t * QKV_N + g * 768 + s * 128;
    const float x1 = qkv[base + d];
    const float x2 = qkv[base + d + 64];
    const float c1 = cosb[t * 128 + d], s1 = sinb[t * 128 + d];
    const float c2 = cosb[t * 128 + d + 64], s2 = sinb[t * 128 + d + 64];
    qkv[base + d]      = x1 * c1 - x2 * s1;
    qkv[base + d + 64] = x2 * c2 + x1 * s2;
}

// ---------------- scale_t[h][t] = mean_d relu_scaling[t][h*128+d] ----------------
__global__ __launch_bounds__(256) void scale_mean_kernel(const float* __restrict__ scaling,
                                                         float* __restrict__ scale_t) {
    const int wid = (blockIdx.x * 256 + threadIdx.x) >> 5;
    const int lane = threadIdx.x & 31;
    const int t = wid >> 5;
    const int h = wid & 31;
    const float4 v = *(const float4*)(scaling + (long)t * C_EMB + h * 128 + lane * 4);
    float s = v.x + v.y + v.z + v.w;
#pragma unroll
    for (int o = 16; o; o >>= 1) s += __shfl_xor_sync(0xffffffffu, s, o);
    if (lane == 0) scale_t[h * T_SEQ + t] = s * (1.f / 128.f);
}

// ---------------- flash attention (non-causal), BQ=64, BK=64 ----------------
#define FLASH_SMEM_FLOATS (3 * 64 * 128 + 64 * 65 + 3 * 64)
#define FLASH_SMEM_BYTES (FLASH_SMEM_FLOATS * 4)

__device__ __forceinline__ int swz(int row, int dv) {
    return row * 128 + ((dv ^ ((row >> 2) & 7)) << 2);
}

__global__ __launch_bounds__(256, 1)
void flash_kernel(const float* __restrict__ qkv, const float* __restrict__ scale_t,
                  float* __restrict__ y) {
    extern __shared__ float sm[];
    float* Sq = sm;
    float* Sk = Sq + 64 * 128;
    float* Sv = Sk + 64 * 128;
    float* S  = Sv + 64 * 128;
    float* m_s = S + 64 * 65;
    float* l_s = m_s + 64;
    float* c_s = l_s + 64;

    const int tid = threadIdx.x;
    const int qb = blockIdx.x;
    const int h = blockIdx.y;
    const int g = h >> 2, s = h & 3;
    const float sf = 0.08838834764831845f;

#pragma unroll
    for (int it = 0; it < 8; ++it) {
        const int f = tid + it * 256;
        const int qi = f >> 5;
        const int dv = f & 31;
        const int t = qb * 64 + qi;
        const float sc = sf * scale_t[h * T_SEQ + t];
        float4 v = *(const float4*)(qkv + (long)t * QKV_N + g * 768 + s * 128 + dv * 4);
        v.x *= sc; v.y *= sc; v.z *= sc; v.w *= sc;
        *(float4*)(Sq + qi * 128 + dv * 4) = v;
    }
    if (tid < 64) { m_s[tid] = -1e30f; l_s[tid] = 0.f; }

    float acc[4][8];
#pragma unroll
    for (int i = 0; i < 4; i++)
#pragma unroll
        for (int j = 0; j < 8; j++) acc[i][j] = 0.f;

    const int r0 = (tid & 15) * 4;
    const int c0 = (tid >> 4) * 8;
    const int q0 = (tid >> 4) * 4;
    const int k0 = (tid & 15) * 4;
    __syncthreads();

    for (int kt = 0; kt < 32; ++kt) {
#pragma unroll
        for (int it = 0; it < 8; ++it) {
            const int f = tid + it * 256;
            const int kj = f >> 5;
            const int dv = f & 31;
            const long base = (long)(kt * 64 + kj) * QKV_N + g * 768;
            *(float4*)(Sk + swz(kj, dv)) = *(const float4*)(qkv + base + 4 * 128 + dv * 4);
            *(float4*)(Sv + swz(kj, dv)) = *(const float4*)(qkv + base + 5 * 128 + dv * 4);
        }
        __syncthreads();

        float sacc[4][4];
#pragma unroll
        for (int i = 0; i < 4; i++)
#pragma unroll
            for (int j = 0; j < 4; j++) sacc[i][j] = 0.f;
        for (int d = 0; d < 128; d += 4) {
            float4 a[4], b[4];
#pragma unroll
            for (int i = 0; i < 4; i++) a[i] = *(const float4*)(Sq + (q0 + i) * 128 + d);
#pragma unroll
            for (int j = 0; j < 4; j++) b[j] = *(const float4*)(Sk + swz(k0 + j, d >> 2));
#pragma unroll
            for (int i = 0; i < 4; i++)
#pragma unroll
                for (int j = 0; j < 4; j++)
                    sacc[i][j] += a[i].x * b[j].x + a[i].y * b[j].y + a[i].z * b[j].z + a[i].w * b[j].w;
        }
#pragma unroll
        for (int i = 0; i < 4; i++)
#pragma unroll
            for (int j = 0; j < 4; j++) S[(q0 + i) * 65 + k0 + j] = sacc[i][j];
        __syncthreads();

        {
            const int r = tid >> 2, qd = tid & 3;
            float* row = S + r * 65;
            float tmax = -1e30f;
            for (int j = qd * 16; j < qd * 16 + 16; j++) tmax = fmaxf(tmax, row[j]);
            tmax = fmaxf(tmax, __shfl_xor_sync(0xffffffffu, tmax, 1));
            tmax = fmaxf(tmax, __shfl_xor_sync(0xffffffffu, tmax, 2));
            const float m_old = m_s[r];
            const float m_new = fmaxf(m_old, tmax);
            float psum = 0.f;
            for (int j = qd * 16; j < qd * 16 + 16; j++) {
                const float p = __expf(row[j] - m_new);
                row[j] = p;
                psum += p;
            }
            psum += __shfl_xor_sync(0xffffffffu, psum, 1);
            psum += __shfl_xor_sync(0xffffffffu, psum, 2);
            if (qd == 0) {
                const float corr = __expf(m_old - m_new);
                l_s[r] = l_s[r] * corr + psum;
                m_s[r] = m_new;
                c_s[r] = corr;
            }
        }
        __syncthreads();

        float cr[4];
#pragma unroll
        for (int i = 0; i < 4; i++) cr[i] = c_s[r0 + i];
#pragma unroll
        for (int i = 0; i < 4; i++)
#pragma unroll
            for (int j = 0; j < 8; j++) acc[i][j] *= cr[i];
        for (int kj = 0; kj < 64; ++kj) {
            float p[4];
#pragma unroll
            for (int i = 0; i < 4; i++) p[i] = S[(r0 + i) * 65 + kj];
            const float4 v0 = *(const float4*)(Sv + swz(kj, c0 >> 2));
            const float4 v1 = *(const float4*)(Sv + swz(kj, (c0 >> 2) + 1));
#pragma unroll
            for (int i = 0; i < 4; i++) {
                acc[i][0] += p[i] * v0.x; acc[i][1] += p[i] * v0.y;
                acc[i][2] += p[i] * v0.z; acc[i][3] += p[i] * v0.w;
                acc[i][4] += p[i] * v1.x; acc[i][5] += p[i] * v1.y;
                acc[i][6] += p[i] * v1.z; acc[i][7] += p[i] * v1.w;
            }
        }
        __syncthreads();
    }

#pragma unroll
    for (int i = 0; i < 4; i++) {
        const int t = qb * 64 + r0 + i;
        const float inv_l = 1.f / l_s[r0 + i];
        float4 o0, o1;
        o0.x = acc[i][0] * inv_l; o0.y = acc[i][1] * inv_l;
        o0.z = acc[i][2] * inv_l; o0.w = acc[i][3] * inv_l;
        o1.x = acc[i][4] * inv_l; o1.y = acc[i][5] * inv_l;
        o1.z = acc[i][6] * inv_l; o1.w = acc[i][7] * inv_l;
        *(float4*)(y + (long)t * C_EMB + h * 128 + c0)     = o0;
        *(float4*)(y + (long)t * C_EMB + h * 128 + c0 + 4) = o1;
    }
}

// ---------------- host launcher ----------------
extern "C" void kernel_launch(void* const* d_in, const int* in_sizes, int n_in,
                              void* d_out, int out_size) {
    const float* x       = (const float*)d_in[0];
    const float* cosb    = (const float*)d_in[1];
    const float* sinb    = (const float*)d_in[2];
    const float* norm1_w = (const float*)d_in[3];
    const float* norm2_w = (const float*)d_in[4];
    const float* attn_w  = (const float*)d_in[5];
    const float* proj_w  = (const float*)d_in[6];
    const float* scale_w = (const float*)d_in[7];
    const float* scale_b = (const float*)d_in[8];
    const float* gate_w  = (const float*)d_in[9];
    const float* up_w    = (const float*)d_in[10];
    const float* down_w  = (const float*)d_in[11];
    float* out = (float*)d_out;

    float *n1, *qkv, *scaling, *scale_t, *y, *resid, *n2, *gate, *hbuf;
    cudaGetSymbolAddress((void**)&n1, g_n1);
    cudaGetSymbolAddress((void**)&qkv, g_qkv);
    cudaGetSymbolAddress((void**)&scaling, g_scaling);
    cudaGetSymbolAddress((void**)&scale_t, g_scale_t);
    cudaGetSymbolAddress((void**)&y, g_y);
    cudaGetSymbolAddress((void**)&resid, g_resid);
    cudaGetSymbolAddress((void**)&n2, g_n2);
    cudaGetSymbolAddress((void**)&gate, g_gate);
    cudaGetSymbolAddress((void**)&hbuf, g_h);

    cudaFuncSetAttribute(flash_kernel, cudaFuncAttributeMaxDynamicSharedMemorySize,
                         FLASH_SMEM_BYTES);

    // n1 = rmsnorm(x, norm1_w)
    rmsnorm_kernel<<<T_SEQ, 256>>>(x, norm1_w, n1);
    // qkv = n1 @ attn_w^T
    tf32_gemm<0><<<dim3(QKV_N / 128, T_SEQ / 128), 256>>>(n1, attn_w, qkv, T_SEQ, QKV_N, C_EMB, nullptr, nullptr);
    // scaling = relu(n1 @ scale_w^T + scale_b)
    tf32_gemm<1><<<dim3(C_EMB / 128, T_SEQ / 128), 256>>>(n1, scale_w, scaling, T_SEQ, C_EMB, C_EMB, nullptr, scale_b);
    // rope in-place on q and k slots
    rope_kernel<<<(T_SEQ * 8 * 5 * 64) / 256, 256>>>(qkv, cosb, sinb);
    // scale_t[h][t] = mean over head dims
    scale_mean_kernel<<<(T_SEQ * N_HEAD_) / 8, 256>>>(scaling, scale_t);
    // flash attention -> y [T][C]
    flash_kernel<<<dim3(T_SEQ / 64, N_HEAD_), 256, FLASH_SMEM_BYTES>>>(qkv, scale_t, y);
    // resid = x + y @ proj_w^T
    tf32_gemm<2><<<dim3(C_EMB / 128, T_SEQ / 128), 256>>>(y, proj_w, resid, T_SEQ, C_EMB, C_EMB, x, nullptr);
    // n2 = rmsnorm(resid, norm2_w)
    rmsnorm_kernel<<<T_SEQ, 256>>>(resid, norm2_w, n2);
    // gate = n2 @ gate_w^T
    tf32_gemm<0><<<dim3(FFN_N / 128, T_SEQ / 128), 256>>>(n2, gate_w, gate, T_SEQ, FFN_N, C_EMB, nullptr, nullptr);
    // hbuf = silu(gate) * (n2 @ up_w^T)
    tf32_gemm<3><<<dim3(FFN_N / 128, T_SEQ / 128), 256>>>(n2, up_w, hbuf, T_SEQ, FFN_N, C_EMB, gate, nullptr);
    // out = resid + hbuf @ down_w^T
    tf32_gemm<2><<<dim3(C_EMB / 128, T_SEQ / 128), 256>>>(hbuf, down_w, out, T_SEQ, C_EMB, FFN_N, resid, nullptr);
}